// round 12
// baseline (speedup 1.0000x reference)
#include <cuda_runtime.h>
#include <cuda_fp16.h>
#include <mma.h>
#include <cstdint>

using namespace nvcuda;

#define BATCH  16384
#define HDIM   1024
#define KTOT   2048
#define WROWS  5120          // 5 gates * 1024
#define BM     128           // batch rows per CTA
#define HB     64            // h columns per CTA
#define NG     320           // 5 gates * HB
#define BK     32            // K per stage
#define NCHUNK (KTOT / BK)   // 64 stages, processed 2 per barrier
#define LDSLD  40            // fp16 leading dim: 80B pitch, conflict-free LDSM
#define NSTAGE 6

// Stage layout (bytes): A [128][40] fp16 = 10240, B [320][40] fp16 = 25600
#define A_OFF 0
#define B_OFF 10240
#define STAGE 35840
#define GLD   324            // gates smem row stride (floats): 320 + 4 pad
#define BSUM_OFF (128 * GLD * 4)          // 165888 (inside stage region, used post-loop)
#define SMEM_REQ (NSTAGE * STAGE + 1536)  // 216576

// Preprocessed fp16 operands (static device scratch, 84 MB)
__device__ __half g_Ah[(size_t)BATCH * KTOT];
__device__ __half g_Wh[(size_t)WROWS * KTOT];

__device__ __forceinline__ float sigmoidf_fast(float v) { return 1.0f / (1.0f + __expf(-v)); }
__device__ __forceinline__ uint32_t smem_u32(const void* p) {
    uint32_t a;
    asm("{ .reg .u64 t; cvta.to.shared.u64 t, %1; cvt.u32.u64 %0, t; }" : "=r"(a) : "l"(p));
    return a;
}
__device__ __forceinline__ void cpasync16(uint32_t dst, const void* src) {
    asm volatile("cp.async.cg.shared.global [%0], [%1], 16;" :: "r"(dst), "l"(src));
}
__device__ __forceinline__ void cp_commit() { asm volatile("cp.async.commit_group;" ::: "memory"); }
__device__ __forceinline__ void cp_wait2() { asm volatile("cp.async.wait_group 2;" ::: "memory"); }

// ---------------------------------------------------------------------------
// Preprocess: fp32 -> fp16.  A[16384][2048] = [x|h_prev], W[5120][2048] = [Wx|Uh]
// ---------------------------------------------------------------------------
__global__ __launch_bounds__(256)
void preprocess_kernel(const float* __restrict__ x, const float* __restrict__ h,
                       const float* __restrict__ Wx, const float* __restrict__ Uh)
{
    const size_t A_UNITS = (size_t)BATCH * KTOT / 8;   // 4194304
    const size_t W_UNITS = (size_t)WROWS * KTOT / 8;   // 1310720
    size_t u = (size_t)blockIdx.x * 256 + threadIdx.x;
    if (u >= A_UNITS + W_UNITS) return;

    const float* src;
    __half* dst;
    if (u < A_UNITS) {
        size_t row = u >> 8, col = (u & 255) * 8;
        src = (col < 1024) ? x + row * 1024 + col : h + row * 1024 + (col - 1024);
        dst = g_Ah + row * KTOT + col;
    } else {
        size_t v = u - A_UNITS;
        size_t row = v >> 8, col = (v & 255) * 8;
        src = (col < 1024) ? Wx + row * 1024 + col : Uh + row * 1024 + (col - 1024);
        dst = g_Wh + row * KTOT + col;
    }
    float4 f0 = *(const float4*)src;
    float4 f1 = *(const float4*)(src + 4);
    __half2 o[4];
    o[0] = __floats2half2_rn(f0.x, f0.y);
    o[1] = __floats2half2_rn(f0.z, f0.w);
    o[2] = __floats2half2_rn(f1.x, f1.y);
    o[3] = __floats2half2_rn(f1.z, f1.w);
    *(uint4*)dst = *(uint4*)o;
}

// ---------------------------------------------------------------------------
// GEMM (fp16 single-pass, fp32 acc) + fused LSTM epilogue.
// Warp grid 2(m) x 4(n); warp tile 64 x 80 -> acc[4][5].
// 6-stage cp.async ring; 2 stages (K=64) per barrier.
// ---------------------------------------------------------------------------
__global__ __launch_bounds__(256, 1)
void lstm_mma_kernel(const float* __restrict__ c_prev, const float* __restrict__ dw,
                     const float* __restrict__ bx, const float* __restrict__ bh,
                     float* __restrict__ out)
{
    extern __shared__ char sm[];
    const int tid  = threadIdx.x;
    const int warp = tid >> 5;
    const int m0 = blockIdx.y * BM;
    const int h0 = blockIdx.x * HB;
    const uint32_t smb = smem_u32(sm);

    const int wm = (warp >> 2) * 64;    // 0 or 64
    const int wn = (warp & 3) * 80;     // 0,80,160,240

    wmma::fragment<wmma::accumulator, 16, 16, 16, float> acc[4][5];
    #pragma unroll
    for (int i = 0; i < 4; i++)
        #pragma unroll
        for (int j = 0; j < 5; j++) wmma::fill_fragment(acc[i][j], 0.0f);

    auto issue_stage = [&](int c) {
        const int kk = c * BK;
        const uint32_t base = smb + (c % NSTAGE) * STAGE;
        #pragma unroll
        for (int p = 0; p < 2; p++) {               // A: 512 units of 16B
            int uu = tid + p * 256;
            int row = uu >> 2, seg = uu & 3;
            size_t go = (size_t)(m0 + row) * KTOT + kk + seg * 8;
            cpasync16(base + A_OFF + row * 80 + seg * 16, g_Ah + go);
        }
        #pragma unroll
        for (int p = 0; p < 5; p++) {               // B: 1280 units of 16B
            int uu = tid + p * 256;
            int row = uu >> 2, seg = uu & 3;        // row 0..319
            int wr = (row >> 6) * 1024 + h0 + (row & 63);
            size_t go = (size_t)wr * KTOT + kk + seg * 8;
            cpasync16(base + B_OFF + row * 80 + seg * 16, g_Wh + go);
        }
    };
    auto mma_stage = [&](int c) {
        const char* st = sm + (c % NSTAGE) * STAGE;
        const __half* Ah = (const __half*)(st + A_OFF);
        const __half* Bh = (const __half*)(st + B_OFF);
        #pragma unroll
        for (int ks = 0; ks < BK; ks += 16) {
            wmma::fragment<wmma::matrix_a, 16, 16, 16, __half, wmma::row_major> ahf[4];
            #pragma unroll
            for (int i2 = 0; i2 < 4; i2++)
                wmma::load_matrix_sync(ahf[i2], Ah + (wm + i2 * 16) * LDSLD + ks, LDSLD);
            #pragma unroll
            for (int j = 0; j < 5; j++) {
                wmma::fragment<wmma::matrix_b, 16, 16, 16, __half, wmma::col_major> bhf;
                wmma::load_matrix_sync(bhf, Bh + (wn + j * 16) * LDSLD + ks, LDSLD);
                #pragma unroll
                for (int i2 = 0; i2 < 4; i2++)
                    wmma::mma_sync(acc[i2][j], ahf[i2], bhf, acc[i2][j]);
            }
        }
    };

    // Prologue: stages 0..3 committed (4 groups outstanding).
    #pragma unroll
    for (int c = 0; c < 4; c++) { issue_stage(c); cp_commit(); }

    // Main loop: 2 stages per barrier. Invariant: 4 groups outstanding at head.
    for (int i = 0; i < NCHUNK; i += 2) {
        cp_wait2();            // stages i, i+1 landed
        __syncthreads();

        // Issue next pair first so the LDGs overlap the mma block below.
        if (i + 4 < NCHUNK) issue_stage(i + 4);
        cp_commit();
        if (i + 5 < NCHUNK) issue_stage(i + 5);
        cp_commit();

        mma_stage(i);
        mma_stage(i + 1);
    }
    __syncthreads();           // all fragment loads done before smem reuse

    // ---- stage gates in smem ----------------------------------------------
    float* gates = (float*)sm;                 // [128][GLD]
    float* bsum  = (float*)(sm + BSUM_OFF);    // [320]
    #pragma unroll
    for (int i2 = 0; i2 < 4; i2++)
        #pragma unroll
        for (int j = 0; j < 5; j++)
            wmma::store_matrix_sync(gates + (wm + i2 * 16) * GLD + wn + j * 16, acc[i2][j],
                                    GLD, wmma::mem_row_major);
    for (int i = tid; i < NG; i += 256) {
        int g = i >> 6, c = i & 63;
        int gi = g * 1024 + h0 + c;
        bsum[i] = bx[gi] + bh[gi];
    }
    __syncthreads();

    // ---- fused LSTM epilogue: 128*64 elems, 32/thread ----------------------
    #pragma unroll
    for (int p = 0; p < 32; p++) {
        int lin = p * 256 + tid;
        int r = lin >> 6;                // 0..127
        int c = lin & 63;                // 0..63
        size_t gidx = (size_t)(m0 + r) * 1024 + h0 + c;
        const float* gr = gates + r * GLD;

        float gi_ = gr[c]        + bsum[c];
        float gf_ = gr[64 + c]   + bsum[64 + c];
        float go_ = gr[128 + c]  + bsum[128 + c];
        float gc_ = gr[192 + c]  + bsum[192 + c];
        float gs_ = gr[256 + c]  + bsum[256 + c];

        float i_t   = sigmoidf_fast(gi_);
        float f_t   = sigmoidf_fast(gf_);
        float o_t   = sigmoidf_fast(go_);
        float c_hat = tanhf(gc_);
        float s_t   = sigmoidf_fast(gs_) * dw[gidx];

        float c_t = f_t * c_prev[gidx] + i_t * c_hat * s_t;
        float h_t = o_t * tanhf(c_t);

        out[gidx] = h_t;
        out[(size_t)BATCH * HDIM + gidx] = c_t;
    }
}

// ---------------------------------------------------------------------------
// Inputs (metadata order): x, h_prev, c_prev, dynamic_weight, Wx, bx, Uh, bh
// ---------------------------------------------------------------------------
extern "C" void kernel_launch(void* const* d_in, const int* in_sizes, int n_in,
                              void* d_out, int out_size)
{
    const float* x  = (const float*)d_in[0];
    const float* hp = (const float*)d_in[1];
    const float* cp = (const float*)d_in[2];
    const float* dw = (const float*)d_in[3];
    const float* Wx = (const float*)d_in[4];
    const float* bx = (const float*)d_in[5];
    const float* Uh = (const float*)d_in[6];
    const float* bh = (const float*)d_in[7];
    float* out = (float*)d_out;

    const size_t total_units = (size_t)BATCH * KTOT / 8 + (size_t)WROWS * KTOT / 8;
    preprocess_kernel<<<(unsigned)((total_units + 255) / 256), 256>>>(x, hp, Wx, Uh);

    cudaFuncSetAttribute(lstm_mma_kernel,
                         cudaFuncAttributeMaxDynamicSharedMemorySize, SMEM_REQ);
    dim3 grid(HDIM / HB, BATCH / BM);   // (16, 128)
    lstm_mma_kernel<<<grid, 256, SMEM_REQ>>>(cp, dw, bx, bh, out);
}

// round 13
// speedup vs baseline: 1.2880x; 1.2880x over previous
#include <cuda_runtime.h>
#include <cuda_fp16.h>
#include <mma.h>
#include <cstdint>

using namespace nvcuda;

#define BATCH  16384
#define HDIM   1024
#define KTOT   2048
#define WROWS  5120          // 5 gates * 1024
#define BM     256           // batch rows per CTA
#define HB     32            // h columns per CTA
#define NG     160           // 5 gates * HB
#define BK     32            // K per stage
#define NCHUNK (KTOT / BK)   // 64
#define LDSLD  40            // fp16 leading dim: 80B pitch, conflict-free LDSM
#define NSTAGE 4
#define NTHREADS 512

// Stage layout (bytes): A [256][40] fp16 = 20480, B [160][40] fp16 = 12800
#define A_OFF 0
#define B_OFF 20480
#define STAGE 33280
#define GLD   164            // gates smem row stride (floats): 160 + 4 pad
#define GATES_BYTES (BM * GLD * 4)        // 167936
#define BSUM_OFF GATES_BYTES
#define SMEM_REQ (GATES_BYTES + 1024)     // 168960 (covers 4*STAGE=133120 too)

// Preprocessed fp16 operands (static device scratch, 84 MB)
__device__ __half g_Ah[(size_t)BATCH * KTOT];
__device__ __half g_Wh[(size_t)WROWS * KTOT];

__device__ __forceinline__ float sigmoidf_fast(float v) { return 1.0f / (1.0f + __expf(-v)); }
__device__ __forceinline__ uint32_t smem_u32(const void* p) {
    uint32_t a;
    asm("{ .reg .u64 t; cvta.to.shared.u64 t, %1; cvt.u32.u64 %0, t; }" : "=r"(a) : "l"(p));
    return a;
}
__device__ __forceinline__ void cpasync16(uint32_t dst, const void* src) {
    asm volatile("cp.async.cg.shared.global [%0], [%1], 16;" :: "r"(dst), "l"(src));
}
__device__ __forceinline__ void cp_commit() { asm volatile("cp.async.commit_group;" ::: "memory"); }
__device__ __forceinline__ void cp_wait2() { asm volatile("cp.async.wait_group 2;" ::: "memory"); }

// ---------------------------------------------------------------------------
// Preprocess: fp32 -> fp16.  A[16384][2048] = [x|h_prev], W[5120][2048] = [Wx|Uh]
// ---------------------------------------------------------------------------
__global__ __launch_bounds__(256)
void preprocess_kernel(const float* __restrict__ x, const float* __restrict__ h,
                       const float* __restrict__ Wx, const float* __restrict__ Uh)
{
    const size_t A_UNITS = (size_t)BATCH * KTOT / 8;   // 4194304
    const size_t W_UNITS = (size_t)WROWS * KTOT / 8;   // 1310720
    size_t u = (size_t)blockIdx.x * 256 + threadIdx.x;
    if (u >= A_UNITS + W_UNITS) return;

    const float* src;
    __half* dst;
    if (u < A_UNITS) {
        size_t row = u >> 8, col = (u & 255) * 8;
        src = (col < 1024) ? x + row * 1024 + col : h + row * 1024 + (col - 1024);
        dst = g_Ah + row * KTOT + col;
    } else {
        size_t v = u - A_UNITS;
        size_t row = v >> 8, col = (v & 255) * 8;
        src = (col < 1024) ? Wx + row * 1024 + col : Uh + row * 1024 + (col - 1024);
        dst = g_Wh + row * KTOT + col;
    }
    float4 f0 = *(const float4*)src;
    float4 f1 = *(const float4*)(src + 4);
    __half2 o[4];
    o[0] = __floats2half2_rn(f0.x, f0.y);
    o[1] = __floats2half2_rn(f0.z, f0.w);
    o[2] = __floats2half2_rn(f1.x, f1.y);
    o[3] = __floats2half2_rn(f1.z, f1.w);
    *(uint4*)dst = *(uint4*)o;
}

// ---------------------------------------------------------------------------
// GEMM (fp16 single-pass, fp32 acc) + fused LSTM epilogue.
// 512 threads, warp grid 8(m) x 2(n); warp tile 32 x 80 -> acc[2][5].
// 4-stage cp.async ring, one K=32 stage per barrier (R11-proven shape).
// ---------------------------------------------------------------------------
__global__ __launch_bounds__(NTHREADS, 1)
void lstm_mma_kernel(const float* __restrict__ c_prev, const float* __restrict__ dw,
                     const float* __restrict__ bx, const float* __restrict__ bh,
                     float* __restrict__ out)
{
    extern __shared__ char sm[];
    const int tid  = threadIdx.x;
    const int warp = tid >> 5;
    const int m0 = blockIdx.y * BM;
    const int h0 = blockIdx.x * HB;
    const uint32_t smb = smem_u32(sm);

    const int wm = (warp >> 1) * 32;    // 0..224
    const int wn = (warp & 1) * 80;     // 0 or 80

    wmma::fragment<wmma::accumulator, 16, 16, 16, float> acc[2][5];
    #pragma unroll
    for (int i = 0; i < 2; i++)
        #pragma unroll
        for (int j = 0; j < 5; j++) wmma::fill_fragment(acc[i][j], 0.0f);

    auto issue_stage = [&](int c) {
        const int kk = c * BK;
        const uint32_t base = smb + (c & (NSTAGE - 1)) * STAGE;
        #pragma unroll
        for (int p = 0; p < 2; p++) {               // A: 1024 units of 16B
            int uu = tid + p * NTHREADS;
            int row = uu >> 2, seg = uu & 3;
            size_t go = (size_t)(m0 + row) * KTOT + kk + seg * 8;
            cpasync16(base + A_OFF + row * 80 + seg * 16, g_Ah + go);
        }
        #pragma unroll
        for (int p = 0; p < 2; p++) {               // B: 640 units of 16B
            if (p == 0 || tid < 128) {
                int uu = tid + p * NTHREADS;
                int row = uu >> 2, seg = uu & 3;    // row 0..159
                int wr = (row >> 5) * 1024 + h0 + (row & 31);
                size_t go = (size_t)wr * KTOT + kk + seg * 8;
                cpasync16(base + B_OFF + row * 80 + seg * 16, g_Wh + go);
            }
        }
    };

    // Prologue: stages 0..2 in flight.
    #pragma unroll
    for (int c = 0; c < 3; c++) { issue_stage(c); cp_commit(); }

    for (int i = 0; i < NCHUNK; i++) {
        cp_wait2();            // stage i landed
        __syncthreads();

        const char* st = sm + (i & (NSTAGE - 1)) * STAGE;
        const __half* Ah = (const __half*)(st + A_OFF);
        const __half* Bh = (const __half*)(st + B_OFF);

        #pragma unroll
        for (int ks = 0; ks < BK; ks += 16) {
            wmma::fragment<wmma::matrix_a, 16, 16, 16, __half, wmma::row_major> ahf[2];
            #pragma unroll
            for (int i2 = 0; i2 < 2; i2++)
                wmma::load_matrix_sync(ahf[i2], Ah + (wm + i2 * 16) * LDSLD + ks, LDSLD);
            #pragma unroll
            for (int j = 0; j < 5; j++) {
                wmma::fragment<wmma::matrix_b, 16, 16, 16, __half, wmma::col_major> bhf;
                wmma::load_matrix_sync(bhf, Bh + (wn + j * 16) * LDSLD + ks, LDSLD);
                #pragma unroll
                for (int i2 = 0; i2 < 2; i2++)
                    wmma::mma_sync(acc[i2][j], ahf[i2], bhf, acc[i2][j]);
            }
        }
        if (i + 3 < NCHUNK) issue_stage(i + 3);
        cp_commit();
    }
    __syncthreads();           // all fragment loads done before smem reuse

    // ---- stage gates in smem ----------------------------------------------
    float* gates = (float*)sm;                 // [256][GLD]
    float* bsum  = (float*)(sm + BSUM_OFF);    // [160]
    #pragma unroll
    for (int i2 = 0; i2 < 2; i2++)
        #pragma unroll
        for (int j = 0; j < 5; j++)
            wmma::store_matrix_sync(gates + (wm + i2 * 16) * GLD + wn + j * 16, acc[i2][j],
                                    GLD, wmma::mem_row_major);
    if (tid < NG) {
        int g = tid >> 5, c = tid & 31;
        int gi = g * 1024 + h0 + c;
        bsum[tid] = bx[gi] + bh[gi];
    }
    __syncthreads();

    // ---- fused LSTM epilogue: 256*32 elems, 16/thread ----------------------
    #pragma unroll
    for (int p = 0; p < 16; p++) {
        int lin = p * NTHREADS + tid;
        int r = lin >> 5;                // 0..255
        int c = lin & 31;                // 0..31
        size_t gidx = (size_t)(m0 + r) * 1024 + h0 + c;
        const float* gr = gates + r * GLD;

        float gi_ = gr[c]        + bsum[c];
        float gf_ = gr[32 + c]   + bsum[32 + c];
        float go_ = gr[64 + c]   + bsum[64 + c];
        float gc_ = gr[96 + c]   + bsum[96 + c];
        float gs_ = gr[128 + c]  + bsum[128 + c];

        float i_t   = sigmoidf_fast(gi_);
        float f_t   = sigmoidf_fast(gf_);
        float o_t   = sigmoidf_fast(go_);
        float c_hat = tanhf(gc_);
        float s_t   = sigmoidf_fast(gs_) * dw[gidx];

        float c_t = f_t * c_prev[gidx] + i_t * c_hat * s_t;
        float h_t = o_t * tanhf(c_t);

        out[gidx] = h_t;
        out[(size_t)BATCH * HDIM + gidx] = c_t;
    }
}

// ---------------------------------------------------------------------------
// Inputs (metadata order): x, h_prev, c_prev, dynamic_weight, Wx, bx, Uh, bh
// ---------------------------------------------------------------------------
extern "C" void kernel_launch(void* const* d_in, const int* in_sizes, int n_in,
                              void* d_out, int out_size)
{
    const float* x  = (const float*)d_in[0];
    const float* hp = (const float*)d_in[1];
    const float* cp = (const float*)d_in[2];
    const float* dw = (const float*)d_in[3];
    const float* Wx = (const float*)d_in[4];
    const float* bx = (const float*)d_in[5];
    const float* Uh = (const float*)d_in[6];
    const float* bh = (const float*)d_in[7];
    float* out = (float*)d_out;

    const size_t total_units = (size_t)BATCH * KTOT / 8 + (size_t)WROWS * KTOT / 8;
    preprocess_kernel<<<(unsigned)((total_units + 255) / 256), 256>>>(x, hp, Wx, Uh);

    cudaFuncSetAttribute(lstm_mma_kernel,
                         cudaFuncAttributeMaxDynamicSharedMemorySize, SMEM_REQ);
    dim3 grid(HDIM / HB, BATCH / BM);   // (32, 64)
    lstm_mma_kernel<<<grid, NTHREADS, SMEM_REQ>>>(cp, dw, bx, bh, out);
}

// round 14
// speedup vs baseline: 1.4345x; 1.1137x over previous
#include <cuda_runtime.h>
#include <cuda_fp16.h>
#include <mma.h>
#include <cstdint>

using namespace nvcuda;

#define BATCH  16384
#define HDIM   1024
#define KTOT   2048
#define WROWS  5120          // 5 gates * 1024
#define BM     128           // batch rows per CTA
#define HB     32            // h columns per CTA
#define NG     160           // 5 gates * HB
#define BK     32            // K per stage
#define NCHUNK (KTOT / BK)   // 64
#define LDSLD  40            // fp16 leading dim: 80B pitch, conflict-free LDSM
#define NSTAGE 4
#define NTHREADS 256

// Stage layout (bytes): A [128][40] fp16 = 10240, B [160][40] fp16 = 12800
#define A_OFF 0
#define B_OFF 10240
#define STAGE 23040
#define GLD   164            // gates smem row stride (floats): 160 + 4 pad
#define BSUM_OFF (NSTAGE * STAGE)         // 92160 (gates reuse: 128*164*4 = 83968 fits below)
#define SMEM_REQ (BSUM_OFF + 1024)        // 93184 -> 2 CTAs = 186368 <= 227KB

// Preprocessed fp16 operands (static device scratch, 84 MB)
__device__ __half g_Ah[(size_t)BATCH * KTOT];
__device__ __half g_Wh[(size_t)WROWS * KTOT];

__device__ __forceinline__ float sigmoidf_fast(float v) { return 1.0f / (1.0f + __expf(-v)); }
__device__ __forceinline__ uint32_t smem_u32(const void* p) {
    uint32_t a;
    asm("{ .reg .u64 t; cvta.to.shared.u64 t, %1; cvt.u32.u64 %0, t; }" : "=r"(a) : "l"(p));
    return a;
}
__device__ __forceinline__ void cpasync16(uint32_t dst, const void* src) {
    asm volatile("cp.async.cg.shared.global [%0], [%1], 16;" :: "r"(dst), "l"(src));
}
__device__ __forceinline__ void cp_commit() { asm volatile("cp.async.commit_group;" ::: "memory"); }
__device__ __forceinline__ void cp_wait2() { asm volatile("cp.async.wait_group 2;" ::: "memory"); }

// ---------------------------------------------------------------------------
// Preprocess: fp32 -> fp16.  A[16384][2048] = [x|h_prev], W[5120][2048] = [Wx|Uh]
// ---------------------------------------------------------------------------
__global__ __launch_bounds__(256)
void preprocess_kernel(const float* __restrict__ x, const float* __restrict__ h,
                       const float* __restrict__ Wx, const float* __restrict__ Uh)
{
    const size_t A_UNITS = (size_t)BATCH * KTOT / 8;   // 4194304
    const size_t W_UNITS = (size_t)WROWS * KTOT / 8;   // 1310720
    size_t u = (size_t)blockIdx.x * 256 + threadIdx.x;
    if (u >= A_UNITS + W_UNITS) return;

    const float* src;
    __half* dst;
    if (u < A_UNITS) {
        size_t row = u >> 8, col = (u & 255) * 8;
        src = (col < 1024) ? x + row * 1024 + col : h + row * 1024 + (col - 1024);
        dst = g_Ah + row * KTOT + col;
    } else {
        size_t v = u - A_UNITS;
        size_t row = v >> 8, col = (v & 255) * 8;
        src = (col < 1024) ? Wx + row * 1024 + col : Uh + row * 1024 + (col - 1024);
        dst = g_Wh + row * KTOT + col;
    }
    float4 f0 = *(const float4*)src;
    float4 f1 = *(const float4*)(src + 4);
    __half2 o[4];
    o[0] = __floats2half2_rn(f0.x, f0.y);
    o[1] = __floats2half2_rn(f0.z, f0.w);
    o[2] = __floats2half2_rn(f1.x, f1.y);
    o[3] = __floats2half2_rn(f1.z, f1.w);
    *(uint4*)dst = *(uint4*)o;
}

// ---------------------------------------------------------------------------
// GEMM (fp16 single-pass, fp32 acc) + fused LSTM epilogue.
// 256 threads, 2 CTAs/SM. Warp grid 4(m) x 2(n); warp tile 32 x 80 -> acc[2][5].
// 4-stage cp.async ring, one K=32 stage per barrier.
// ---------------------------------------------------------------------------
__global__ __launch_bounds__(NTHREADS, 2)
void lstm_mma_kernel(const float* __restrict__ c_prev, const float* __restrict__ dw,
                     const float* __restrict__ bx, const float* __restrict__ bh,
                     float* __restrict__ out)
{
    extern __shared__ char sm[];
    const int tid  = threadIdx.x;
    const int warp = tid >> 5;
    const int m0 = blockIdx.y * BM;
    const int h0 = blockIdx.x * HB;
    const uint32_t smb = smem_u32(sm);

    const int wm = (warp & 3) * 32;     // 0..96
    const int wn = (warp >> 2) * 80;    // 0 or 80

    wmma::fragment<wmma::accumulator, 16, 16, 16, float> acc[2][5];
    #pragma unroll
    for (int i = 0; i < 2; i++)
        #pragma unroll
        for (int j = 0; j < 5; j++) wmma::fill_fragment(acc[i][j], 0.0f);

    auto issue_stage = [&](int c) {
        const int kk = c * BK;
        const uint32_t base = smb + (c & (NSTAGE - 1)) * STAGE;
        #pragma unroll
        for (int p = 0; p < 2; p++) {               // A: 512 units of 16B
            int uu = tid + p * NTHREADS;
            int row = uu >> 2, seg = uu & 3;
            size_t go = (size_t)(m0 + row) * KTOT + kk + seg * 8;
            cpasync16(base + A_OFF + row * 80 + seg * 16, g_Ah + go);
        }
        #pragma unroll
        for (int p = 0; p < 3; p++) {               // B: 640 units of 16B
            if (p < 2 || tid < 128) {
                int uu = tid + p * NTHREADS;
                int row = uu >> 2, seg = uu & 3;    // row 0..159
                int wr = (row >> 5) * 1024 + h0 + (row & 31);
                size_t go = (size_t)wr * KTOT + kk + seg * 8;
                cpasync16(base + B_OFF + row * 80 + seg * 16, g_Wh + go);
            }
        }
    };

    // Prologue: stages 0..2 in flight.
    #pragma unroll
    for (int c = 0; c < 3; c++) { issue_stage(c); cp_commit(); }

    for (int i = 0; i < NCHUNK; i++) {
        cp_wait2();            // stage i landed
        __syncthreads();

        const char* st = sm + (i & (NSTAGE - 1)) * STAGE;
        const __half* Ah = (const __half*)(st + A_OFF);
        const __half* Bh = (const __half*)(st + B_OFF);

        #pragma unroll
        for (int ks = 0; ks < BK; ks += 16) {
            wmma::fragment<wmma::matrix_a, 16, 16, 16, __half, wmma::row_major> ahf[2];
            #pragma unroll
            for (int i2 = 0; i2 < 2; i2++)
                wmma::load_matrix_sync(ahf[i2], Ah + (wm + i2 * 16) * LDSLD + ks, LDSLD);
            #pragma unroll
            for (int j = 0; j < 5; j++) {
                wmma::fragment<wmma::matrix_b, 16, 16, 16, __half, wmma::col_major> bhf;
                wmma::load_matrix_sync(bhf, Bh + (wn + j * 16) * LDSLD + ks, LDSLD);
                #pragma unroll
                for (int i2 = 0; i2 < 2; i2++)
                    wmma::mma_sync(acc[i2][j], ahf[i2], bhf, acc[i2][j]);
            }
        }
        if (i + 3 < NCHUNK) issue_stage(i + 3);
        cp_commit();
    }
    __syncthreads();           // all fragment loads done before smem reuse

    // ---- stage gates in smem ----------------------------------------------
    float* gates = (float*)sm;                 // [128][GLD]
    float* bsum  = (float*)(sm + BSUM_OFF);    // [160]
    #pragma unroll
    for (int i2 = 0; i2 < 2; i2++)
        #pragma unroll
        for (int j = 0; j < 5; j++)
            wmma::store_matrix_sync(gates + (wm + i2 * 16) * GLD + wn + j * 16, acc[i2][j],
                                    GLD, wmma::mem_row_major);
    if (tid < NG) {
        int g = tid >> 5, c = tid & 31;
        int gi = g * 1024 + h0 + c;
        bsum[tid] = bx[gi] + bh[gi];
    }
    __syncthreads();

    // ---- fused LSTM epilogue: 128*32 elems, 16/thread ----------------------
    #pragma unroll
    for (int p = 0; p < 16; p++) {
        int lin = p * NTHREADS + tid;
        int r = lin >> 5;                // 0..127
        int c = lin & 31;                // 0..31
        size_t gidx = (size_t)(m0 + r) * 1024 + h0 + c;
        const float* gr = gates + r * GLD;

        float gi_ = gr[c]        + bsum[c];
        float gf_ = gr[32 + c]   + bsum[32 + c];
        float go_ = gr[64 + c]   + bsum[64 + c];
        float gc_ = gr[96 + c]   + bsum[96 + c];
        float gs_ = gr[128 + c]  + bsum[128 + c];

        float i_t   = sigmoidf_fast(gi_);
        float f_t   = sigmoidf_fast(gf_);
        float o_t   = sigmoidf_fast(go_);
        float c_hat = tanhf(gc_);
        float s_t   = sigmoidf_fast(gs_) * dw[gidx];

        float c_t = f_t * c_prev[gidx] + i_t * c_hat * s_t;
        float h_t = o_t * tanhf(c_t);

        out[gidx] = h_t;
        out[(size_t)BATCH * HDIM + gidx] = c_t;
    }
}

// ---------------------------------------------------------------------------
// Inputs (metadata order): x, h_prev, c_prev, dynamic_weight, Wx, bx, Uh, bh
// ---------------------------------------------------------------------------
extern "C" void kernel_launch(void* const* d_in, const int* in_sizes, int n_in,
                              void* d_out, int out_size)
{
    const float* x  = (const float*)d_in[0];
    const float* hp = (const float*)d_in[1];
    const float* cp = (const float*)d_in[2];
    const float* dw = (const float*)d_in[3];
    const float* Wx = (const float*)d_in[4];
    const float* bx = (const float*)d_in[5];
    const float* Uh = (const float*)d_in[6];
    const float* bh = (const float*)d_in[7];
    float* out = (float*)d_out;

    const size_t total_units = (size_t)BATCH * KTOT / 8 + (size_t)WROWS * KTOT / 8;
    preprocess_kernel<<<(unsigned)((total_units + 255) / 256), 256>>>(x, hp, Wx, Uh);

    cudaFuncSetAttribute(lstm_mma_kernel,
                         cudaFuncAttributeMaxDynamicSharedMemorySize, SMEM_REQ);
    dim3 grid(HDIM / HB, BATCH / BM);   // (32, 128) = 4096 CTAs
    lstm_mma_kernel<<<grid, NTHREADS, SMEM_REQ>>>(cp, dw, bx, bh, out);
}